// round 9
// baseline (speedup 1.0000x reference)
#include <cuda_runtime.h>
#include <cuda_bf16.h>
#include <cstdint>

#define C_DIM  256      // K
#define HW     4096
#define P_TOT  16384    // M total
#define N_SAMP 2048     // N total
#define NPC    512
#define NCLS   4
#define TMG    64       // M tile per CTA (A tile 64x256 bf16 = 32KB)
#define TNB    16       // B tile per iter (16x256 bf16 = 8KB, x2 buffers)
#define NITER  (N_SAMP / TNB)   // 128

// ---------------- scratch (__device__ globals; no allocs allowed) ----------------
__device__ __align__(16) __nv_bfloat16 g_Xbf[P_TOT * C_DIM];   // [pixel][k]
__device__ __align__(16) __nv_bfloat16 g_Pbf[N_SAMP * C_DIM];  // normalized, [n][k]
__device__ float g_inv10[P_TOT];    // 10 / max(||x||, eps)
__device__ int   g_cls[P_TOT];
__device__ int   g_pcls[N_SAMP];

// ---------------- helpers ----------------
static __device__ __forceinline__ uint32_t smem_u32(const void* p) {
    uint32_t a;
    asm("{ .reg .u64 t; cvta.to.shared.u64 t, %1; cvt.u32.u64 %0, t; }" : "=r"(a) : "l"(p));
    return a;
}
// Swizzled byte offset of 16B chunk (row, kchunk) in a [rows][256] bf16 tile
// (row stride 512B; chunk XORed with row&7 -> conflict-free ldmatrix).
static __device__ __forceinline__ uint32_t swz(int row, int kc) {
    return (uint32_t)(row * 512 + ((kc ^ (row & 7)) << 4));
}
static __device__ __forceinline__ void ldm4(uint32_t* r, uint32_t addr) {
    asm volatile("ldmatrix.sync.aligned.m8n8.x4.shared.b16 {%0,%1,%2,%3}, [%4];"
                 : "=r"(r[0]), "=r"(r[1]), "=r"(r[2]), "=r"(r[3]) : "r"(addr));
}
static __device__ __forceinline__ void mma16816(float* d, const uint32_t* a,
                                                uint32_t b0, uint32_t b1) {
    asm volatile(
        "mma.sync.aligned.m16n8k16.row.col.f32.bf16.bf16.f32 "
        "{%0,%1,%2,%3},{%4,%5,%6,%7},{%8,%9},{%0,%1,%2,%3};"
        : "+f"(d[0]), "+f"(d[1]), "+f"(d[2]), "+f"(d[3])
        : "r"(a[0]), "r"(a[1]), "r"(a[2]), "r"(a[3]), "r"(b0), "r"(b1));
}
static __device__ __forceinline__ void cpasync16(uint32_t dst, const void* src) {
    asm volatile("cp.async.cg.shared.global [%0], [%1], 16;" :: "r"(dst), "l"(src));
}
#define CP_COMMIT() asm volatile("cp.async.commit_group;" ::: "memory")
#define CP_WAIT(n)  asm volatile("cp.async.wait_group %0;" :: "n"(n) : "memory")

// ---------------- kernels ----------------
__global__ void zero_kernel(float* out) { if (threadIdx.x == 0) *out = 0.0f; }

// Normalize past samples -> bf16; per-sample class from one-hot labels.
__global__ void pnorm_kernel(const float* __restrict__ P, const float* __restrict__ L) {
    int n = blockIdx.x;
    int t = threadIdx.x;             // = channel
    float v = P[n * C_DIM + t];
    __shared__ float sh[256];
    sh[t] = v * v;
    __syncthreads();
    for (int s = 128; s > 0; s >>= 1) { if (t < s) sh[t] += sh[t + s]; __syncthreads(); }
    float inv = 1.0f / fmaxf(sqrtf(sh[0]), 1e-8f);
    g_Pbf[n * C_DIM + t] = __float2bfloat16(v * inv);
    if (t == 0) {
        int c = 0; float best = -1.0f;
        #pragma unroll
        for (int k = 0; k < NCLS; k++) { float lv = L[n * NCLS + k]; if (lv > best) { best = lv; c = k; } }
        g_pcls[n] = c;
    }
}

// Transpose X [b][c][v] -> g_Xbf[pixel][c] bf16; norms; pixel class.
__global__ void prep_kernel(const float* __restrict__ X, const float* __restrict__ Y) {
    int p = blockIdx.x * 256 + threadIdx.x;
    int b = p >> 12, v = p & 4095;
    const float* xb = X + (size_t)b * C_DIM * HW + v;
    float nrm = 0.0f;
    for (int c0 = 0; c0 < C_DIM; c0 += 8) {
        uint4 pk;
        __nv_bfloat16* bp = (__nv_bfloat16*)&pk;
        #pragma unroll
        for (int j = 0; j < 8; j++) {
            float x = xb[(size_t)(c0 + j) * HW];
            nrm = fmaf(x, x, nrm);
            bp[j] = __float2bfloat16(x);
        }
        *(uint4*)(&g_Xbf[(size_t)p * C_DIM + c0]) = pk;
    }
    g_inv10[p] = 10.0f / fmaxf(sqrtf(nrm), 1e-8f);
    const float* yb = Y + (size_t)b * NCLS * HW + v;
    int cls = 0; float best = -1.0f;
    #pragma unroll
    for (int k = 0; k < NCLS; k++) { float yv = yb[(size_t)k * HW]; if (yv > best) { best = yv; cls = k; } }
    g_cls[p] = cls;
}

// bf16 mma.sync GEMM, double-buffered pipelined B, + exp epilogue + ratio.
// One CTA per 64 pixels; 4 warps 4(M)x1(N); warp tile 16(M)x16(N).
// Static smem 48KB exactly: A 32KB @0, B0 8KB @32768, B1 8KB @40960.
__global__ __launch_bounds__(128) void gemm_kernel(float* __restrict__ out) {
    __shared__ __align__(128) char sm[49152];
    uint32_t sA = smem_u32(sm);
    int t = threadIdx.x, wid = t >> 5, lane = t & 31;
    int m0 = blockIdx.x * TMG;

    // Load A tile: 64 rows x 32 chunks = 2048, 16 per thread. (group 1)
    #pragma unroll
    for (int i = 0; i < 16; i++) {
        int idx = t + i * 128;
        int row = idx >> 5, kc = idx & 31;
        cpasync16(sA + swz(row, kc), g_Xbf + (size_t)(m0 + row) * C_DIM + kc * 8);
    }
    CP_COMMIT();
    // Preload B tile 0: 16 rows x 32 chunks = 512, 4 per thread. (group 2)
    #pragma unroll
    for (int i = 0; i < 4; i++) {
        int idx = t + i * 128;
        int row = idx >> 5, kc = idx & 31;
        cpasync16(sA + 32768u + swz(row, kc), g_Pbf + (size_t)row * C_DIM + kc * 8);
    }
    CP_COMMIT();

    // rows owned by this lane: m0 + wid*16 + s*8 + (lane>>2), s in {0,1}
    float inv_r[2];
    inv_r[0] = g_inv10[m0 + wid * 16 + (lane >> 2)];
    inv_r[1] = g_inv10[m0 + wid * 16 + 8 + (lane >> 2)];

    float cls_acc[2][NCLS];
    #pragma unroll
    for (int s = 0; s < 2; s++)
        #pragma unroll
        for (int c = 0; c < NCLS; c++) cls_acc[s][c] = 0.0f;

    for (int it = 0; it < NITER; it++) {
        uint32_t sB = sA + 32768u + (uint32_t)((it & 1) * 8192);
        // issue prefetch of tile it+1 into the other buffer
        if (it + 1 < NITER) {
            const __nv_bfloat16* bsrc = g_Pbf + (size_t)(it + 1) * TNB * C_DIM;
            uint32_t dst = sA + 32768u + (uint32_t)(((it + 1) & 1) * 8192);
            #pragma unroll
            for (int i = 0; i < 4; i++) {
                int idx = t + i * 128;
                int row = idx >> 5, kc = idx & 31;
                cpasync16(dst + swz(row, kc), bsrc + (size_t)row * C_DIM + kc * 8);
            }
            CP_COMMIT();
            CP_WAIT(1);        // tile it (and A) complete; it+1 still in flight
        } else {
            CP_WAIT(0);
        }
        __syncthreads();

        float d[2][4];
        #pragma unroll
        for (int j = 0; j < 2; j++)
            #pragma unroll
            for (int q = 0; q < 4; q++) d[j][q] = 0.0f;

        #pragma unroll
        for (int ks = 0; ks < 16; ks++) {
            uint32_t a[4], b[4];
            ldm4(a, sA + swz(wid * 16 + (lane & 15), ks * 2 + (lane >> 4)));
            ldm4(b, sB + swz(((lane >> 4) << 3) + (lane & 7), ks * 2 + ((lane >> 3) & 1)));
            mma16816(d[0], a, b[0], b[1]);
            mma16816(d[1], a, b[2], b[3]);
        }

        // epilogue: all 16 cols this iter share one class
        int cls = g_pcls[it * TNB];
        float s0 = 0.0f, s1 = 0.0f;
        #pragma unroll
        for (int j = 0; j < 2; j++) {
            s0 += __expf(fmaf(d[j][0], inv_r[0], -10.0f))
                + __expf(fmaf(d[j][1], inv_r[0], -10.0f));
            s1 += __expf(fmaf(d[j][2], inv_r[1], -10.0f))
                + __expf(fmaf(d[j][3], inv_r[1], -10.0f));
        }
        cls_acc[0][cls] += s0;
        cls_acc[1][cls] += s1;

        __syncthreads();   // all warps done reading sB before it's overwritten
    }

    // ---- reduction: each row owned by exactly one warp -> no atomics ----
    float* sRed = (float*)sm;              // 64 rows x 4 classes
    float* red2 = (float*)(sm + 1024);     // 128 floats block reduce
    #pragma unroll
    for (int s = 0; s < 2; s++) {
        int row = wid * 16 + s * 8 + (lane >> 2);
        #pragma unroll
        for (int c = 0; c < NCLS; c++) {
            float v = cls_acc[s][c];
            v += __shfl_xor_sync(0xFFFFFFFFu, v, 1);
            v += __shfl_xor_sync(0xFFFFFFFFu, v, 2);
            if ((lane & 3) == 0) sRed[row * NCLS + c] = v;
        }
    }
    __syncthreads();

    float rr = 0.0f;
    if (t < TMG) {
        int p = m0 + t;
        int cl = g_cls[p];
        float v0 = sRed[t * 4], v1 = sRed[t * 4 + 1], v2 = sRed[t * 4 + 2], v3 = sRed[t * 4 + 3];
        float tot = v0 + v1 + v2 + v3;
        float sc = (cl == 0) ? v0 : (cl == 1) ? v1 : (cl == 2) ? v2 : v3;
        rr = (sc + (float)(N_SAMP - NPC)) / ((tot - sc) + (float)NPC);
    }
    red2[t] = rr;
    __syncthreads();
    for (int s = 64; s > 0; s >>= 1) { if (t < s) red2[t] += red2[t + s]; __syncthreads(); }
    if (t == 0) atomicAdd(out, red2[0] * (1.0f / (float)P_TOT));
}

extern "C" void kernel_launch(void* const* d_in, const int* in_sizes, int n_in,
                              void* d_out, int out_size) {
    const float* X = (const float*)d_in[0];   // (4,256,64,64)
    const float* Y = (const float*)d_in[1];   // (4,4,64,64)
    const float* P = (const float*)d_in[2];   // (2048,256)
    const float* L = (const float*)d_in[3];   // (2048,4)
    float* out = (float*)d_out;

    zero_kernel<<<1, 32>>>(out);
    pnorm_kernel<<<N_SAMP, 256>>>(P, L);
    prep_kernel<<<P_TOT / 256, 256>>>(X, Y);
    gemm_kernel<<<P_TOT / TMG, 128>>>(out);
}